// round 7
// baseline (speedup 1.0000x reference)
#include <cuda_runtime.h>
#include <math.h>

// ---------------------------------------------------------------------------
// HGGNet: 3-stage point hierarchy. B=8, N=4096 -> 2048 -> 512 -> 128, K=16.
// All scratch lives in one __device__ arena (no allocations anywhere).
// ---------------------------------------------------------------------------

static const int B = 8;

// float-indexed offsets into the arena
static const size_t OFF_EDGE  = 0;          // up to 16,777,216
static const size_t OFF_Y     = 16777216;   // up to 16,777,216
static const size_t OFF_F0    = 33554432;   // 8*8*4096    = 262144
static const size_t OFF_F1    = 33816576;   // 8*32*4096   = 1048576
static const size_t OFF_F1Q   = 34865152;   // 8*32*2048   = 524288
static const size_t OFF_S1    = 35389440;   // 8*64*2048   = 1048576
static const size_t OFF_S1Q   = 36438016;   // 8*64*512    = 262144
static const size_t OFF_F4    = 36700160;   // 8*128*512   = 524288
static const size_t OFF_S2    = 37224448;   // 8*128*512   = 524288
static const size_t OFF_S2Q   = 37748736;   // 8*128*128   = 131072
static const size_t OFF_F6    = 37879808;   // 8*256*128   = 262144
static const size_t OFF_S3    = 38141952;   // 8*256*128   = 262144
static const size_t OFF_C1    = 38404096;   // 8*2048*3    = 49152
static const size_t OFF_C2    = 38453248;   // 8*512*3     = 12288
static const size_t OFF_C3    = 38465536;   // 8*128*3     = 3072
static const size_t OFF_STATS = 38468608;   // 8*4*2       = 64
static const size_t OFF_SEL   = 38468672;   // 8*2048 ints = 16384
static const size_t OFF_KNN   = 38485056;   // 8*4096*16   = 524288
static const size_t ARENA_SZ  = 39009344;

__device__ float g_arena[ARENA_SZ];

// ---------------------------------------------------------------------------
// input projection: f0[b,o,n] = sum_c w[o,c]*x[b,n,c] + bias[o]   (O=8, C=3)
// ---------------------------------------------------------------------------
__global__ void input_proj_kernel(const float* __restrict__ x,
                                  const float* __restrict__ w,
                                  const float* __restrict__ bias,
                                  float* __restrict__ f0) {
    int i = blockIdx.x * blockDim.x + threadIdx.x;   // over B*4096
    if (i >= 8 * 4096) return;
    float x0 = x[i * 3 + 0], x1 = x[i * 3 + 1], x2 = x[i * 3 + 2];
    int b = i >> 12, n = i & 4095;
#pragma unroll
    for (int o = 0; o < 8; o++) {
        float v = __fmaf_rn(x2, w[o * 3 + 2],
                  __fmaf_rn(x1, w[o * 3 + 1], __fmul_rn(x0, w[o * 3 + 0])));
        f0[((size_t)b * 8 + o) * 4096 + n] = v + bias[o];
    }
}

// ---------------------------------------------------------------------------
// kNN(16): brute force, one thread per query, key tiles staged in smem.
// d = (||q||^2 - 2 q.k) + ||k||^2. Ties at the boundary: lower index wins.
// ---------------------------------------------------------------------------
#define KTILE 128
__global__ void knn_kernel(const float* __restrict__ qpts,
                           const float* __restrict__ kpts,
                           int Nq, int Nk, int* __restrict__ out) {
    __shared__ float4 sk[KTILE];
    int b  = blockIdx.y;
    int qi = blockIdx.x * blockDim.x + threadIdx.x;
    float qx = 0.f, qy = 0.f, qz = 0.f, qq = 0.f;
    if (qi < Nq) {
        const float* qp = qpts + ((size_t)b * Nq + qi) * 3;
        qx = qp[0]; qy = qp[1]; qz = qp[2];
        qq = __fadd_rn(__fadd_rn(__fmul_rn(qx, qx), __fmul_rn(qy, qy)),
                       __fmul_rn(qz, qz));
    }
    float bd[16]; int bi[16];
#pragma unroll
    for (int i = 0; i < 16; i++) { bd[i] = 3.4e38f; bi[i] = 0; }
    float worst = 3.4e38f;

    for (int t0 = 0; t0 < Nk; t0 += KTILE) {
        int lim = min(KTILE, Nk - t0);
        __syncthreads();
        for (int j = threadIdx.x; j < lim; j += blockDim.x) {
            const float* kp = kpts + ((size_t)b * Nk + t0 + j) * 3;
            float kx = kp[0], ky = kp[1], kz = kp[2];
            float kk = __fadd_rn(__fadd_rn(__fmul_rn(kx, kx), __fmul_rn(ky, ky)),
                                 __fmul_rn(kz, kz));
            sk[j] = make_float4(kx, ky, kz, kk);
        }
        __syncthreads();
        if (qi < Nq) {
            for (int j = 0; j < lim; j++) {
                float4 kp = sk[j];
                float dot = __fmaf_rn(qz, kp.z,
                            __fmaf_rn(qy, kp.y, __fmul_rn(qx, kp.x)));
                float d = __fadd_rn(__fsub_rn(qq, __fmul_rn(2.0f, dot)), kp.w);
                if (d < worst) {
                    int p = 15;
                    while (p > 0 && bd[p - 1] > d) {
                        bd[p] = bd[p - 1]; bi[p] = bi[p - 1]; --p;
                    }
                    bd[p] = d; bi[p] = t0 + j;
                    worst = bd[15];
                }
            }
        }
    }
    if (qi < Nq) {
        int* o = out + ((size_t)b * Nq + qi) * 16;
#pragma unroll
        for (int i = 0; i < 16; i++) o[i] = bi[i];
    }
}

// ---------------------------------------------------------------------------
// FPS: one 1024-thread block per batch, coords + running min-dist in regs.
// argmax tie-break: lowest index (matches jnp.argmax first occurrence).
// ---------------------------------------------------------------------------
template <int PER>
__global__ void __launch_bounds__(1024)
fps_kernel(const float* __restrict__ coor, int N, int m,
           int* __restrict__ sel, float* __restrict__ outc) {
    int b = blockIdx.x;
    const float* c = coor + (size_t)b * N * 3;
    int t = threadIdx.x;
    const int T = 1024;
    float px[PER], py[PER], pz[PER], dd[PER];
#pragma unroll
    for (int i = 0; i < PER; i++) {
        int id = t + i * T;
        if (id < N) {
            px[i] = c[id * 3 + 0]; py[i] = c[id * 3 + 1]; pz[i] = c[id * 3 + 2];
            dd[i] = 1e10f;
        } else {
            px[i] = py[i] = pz[i] = 0.f;
            dd[i] = -3.0e38f;
        }
    }
    __shared__ float swv[32];
    __shared__ int   swi[32];
    __shared__ int   s_best;
    if (t == 0) sel[(size_t)b * m] = 0;
    int last = 0;
    int lane = t & 31, wid = t >> 5;

    for (int it = 1; it < m; ++it) {
        float lx = c[last * 3 + 0], ly = c[last * 3 + 1], lz = c[last * 3 + 2];
        float bv = -3.4e38f; int bI = 0x7fffffff;
#pragma unroll
        for (int i = 0; i < PER; i++) {
            float dx = __fsub_rn(px[i], lx);
            float dy = __fsub_rn(py[i], ly);
            float dz = __fsub_rn(pz[i], lz);
            float d = __fadd_rn(__fadd_rn(__fmul_rn(dx, dx), __fmul_rn(dy, dy)),
                                __fmul_rn(dz, dz));
            float nd = fminf(dd[i], d);
            dd[i] = nd;
            int id = t + i * T;
            if (nd > bv) { bv = nd; bI = id; }
        }
#pragma unroll
        for (int off = 16; off; off >>= 1) {
            float ov = __shfl_down_sync(0xffffffffu, bv, off);
            int   oi = __shfl_down_sync(0xffffffffu, bI, off);
            if (ov > bv || (ov == bv && oi < bI)) { bv = ov; bI = oi; }
        }
        if (lane == 0) { swv[wid] = bv; swi[wid] = bI; }
        __syncthreads();
        if (wid == 0) {
            bv = swv[lane]; bI = swi[lane];
#pragma unroll
            for (int off = 16; off; off >>= 1) {
                float ov = __shfl_down_sync(0xffffffffu, bv, off);
                int   oi = __shfl_down_sync(0xffffffffu, bI, off);
                if (ov > bv || (ov == bv && oi < bI)) { bv = ov; bI = oi; }
            }
            if (lane == 0) s_best = bI;
        }
        __syncthreads();
        last = s_best;
        if (t == 0) sel[(size_t)b * m + it] = last;
    }
    __syncthreads();
    for (int i = t; i < m; i += T) {
        int s = sel[(size_t)b * m + i];
        outc[((size_t)b * m + i) * 3 + 0] = c[s * 3 + 0];
        outc[((size_t)b * m + i) * 3 + 1] = c[s * 3 + 1];
        outc[((size_t)b * m + i) * 3 + 2] = c[s * 3 + 2];
    }
}

// ---------------------------------------------------------------------------
// feature gather after FPS: out[b,c,i] = f[b,c,sel[b,i]]
// ---------------------------------------------------------------------------
__global__ void gather_feat_kernel(const float* __restrict__ f,
                                   const int* __restrict__ sel,
                                   int C, int Nin, int Nout,
                                   float* __restrict__ out) {
    int i = blockIdx.x * blockDim.x + threadIdx.x;
    if (i >= 8 * C * Nout) return;
    int n = i % Nout;
    int cc = (i / Nout) % C;
    int b = i / (Nout * C);
    out[i] = f[((size_t)b * C + cc) * Nin + sel[(size_t)b * Nout + n]];
}

// ---------------------------------------------------------------------------
// edge features: edge[b,c2,m], m = n*16+k
//   c2 <  C : xk[b,c2,idx[b,n,k]] - xq[b,c2,n]
//   c2 >= C : xq[b,c2-C,n]
// ---------------------------------------------------------------------------
__global__ void edge_kernel(const float* __restrict__ xk,
                            const float* __restrict__ xq,
                            const int* __restrict__ idx, int C, int Nq, int Nk,
                            float* __restrict__ edge) {
    int m = blockIdx.x * blockDim.x + threadIdx.x;
    int M = Nq << 4;
    if (m >= M) return;
    int c2 = blockIdx.y, b = blockIdx.z;
    int n = m >> 4;
    float v;
    if (c2 < C) {
        int j = idx[((size_t)b * Nq + n) * 16 + (m & 15)];
        v = xk[((size_t)b * C + c2) * Nk + j] - xq[((size_t)b * C + c2) * Nq + n];
    } else {
        v = xq[((size_t)b * C + (c2 - C)) * Nq + n];
    }
    edge[((size_t)b * (2 * C) + c2) * M + m] = v;
}

// ---------------------------------------------------------------------------
// batched GEMM: Y[b,o,m] = sum_c W[o,c]*E[b,c,m]
// tile 128(m) x 32(o), kc=16, 256 threads, 4x4 micro-tile.
// Requires M%128==0, O%32==0, K%16==0 (true for all layers).
// ---------------------------------------------------------------------------
__global__ void __launch_bounds__(256)
gemm_kernel(const float* __restrict__ W, const float* __restrict__ E,
            float* __restrict__ Y, int O, int K, int M) {
    __shared__ __align__(16) float sE[16][128];
    __shared__ __align__(16) float sW[16][32];
    int b  = blockIdx.z;
    int m0 = blockIdx.x << 7;
    int o0 = blockIdx.y << 5;
    const float* Eb = E + (size_t)b * K * M;
    int tx = threadIdx.x;
    int tm = tx >> 3;   // 0..31
    int to = tx & 7;    // 0..7
    float acc[4][4];
#pragma unroll
    for (int i = 0; i < 4; i++)
#pragma unroll
        for (int j = 0; j < 4; j++) acc[i][j] = 0.f;

    for (int k0 = 0; k0 < K; k0 += 16) {
#pragma unroll
        for (int e = 0; e < 2; e++) {
            int id = tx + (e << 8);
            sW[id & 15][id >> 4] = W[(o0 + (id >> 4)) * K + k0 + (id & 15)];
        }
#pragma unroll
        for (int e = 0; e < 8; e++) {
            int id = tx + (e << 8);
            sE[id >> 7][id & 127] =
                Eb[(size_t)(k0 + (id >> 7)) * M + m0 + (id & 127)];
        }
        __syncthreads();
#pragma unroll
        for (int c = 0; c < 16; c++) {
            float4 ev = *reinterpret_cast<const float4*>(&sE[c][tm << 2]);
            float4 wv = *reinterpret_cast<const float4*>(&sW[c][to << 2]);
            float em[4] = {ev.x, ev.y, ev.z, ev.w};
            float wo[4] = {wv.x, wv.y, wv.z, wv.w};
#pragma unroll
            for (int mi = 0; mi < 4; mi++)
#pragma unroll
                for (int oi = 0; oi < 4; oi++)
                    acc[mi][oi] = __fmaf_rn(em[mi], wo[oi], acc[mi][oi]);
        }
        __syncthreads();
    }
    float* Yb = Y + (size_t)b * O * M;
#pragma unroll
    for (int oi = 0; oi < 4; oi++) {
        int o = o0 + (to << 2) + oi;
        float4 v = make_float4(acc[0][oi], acc[1][oi], acc[2][oi], acc[3][oi]);
        *reinterpret_cast<float4*>(&Yb[(size_t)o * M + m0 + (tm << 2)]) = v;
    }
}

// ---------------------------------------------------------------------------
// GroupNorm stats: sum & sumsq per (b, group) over (C/4, N, 16)
// ---------------------------------------------------------------------------
__global__ void zero_stats_kernel(float* __restrict__ stats) {
    if (threadIdx.x < 64) stats[threadIdx.x] = 0.f;
}

__global__ void stats_kernel(const float* __restrict__ Y, int O, int M,
                             float* __restrict__ stats) {
    __shared__ float ssum[256], ssq[256];
    int bg = blockIdx.y;
    int b = bg >> 2, g = bg & 3;
    int Cg = O >> 2;
    const float* base = Y + ((size_t)b * O + (size_t)g * Cg) * M;
    size_t cnt = (size_t)Cg * M;
    float s = 0.f, q = 0.f;
    for (size_t i = (size_t)blockIdx.x * blockDim.x + threadIdx.x; i < cnt;
         i += (size_t)gridDim.x * blockDim.x) {
        float v = base[i];
        s += v;
        q = __fmaf_rn(v, v, q);
    }
    int tid = threadIdx.x;
    ssum[tid] = s; ssq[tid] = q;
    __syncthreads();
    for (int o = 128; o; o >>= 1) {
        if (tid < o) { ssum[tid] += ssum[tid + o]; ssq[tid] += ssq[tid + o]; }
        __syncthreads();
    }
    if (tid == 0) {
        atomicAdd(&stats[bg * 2 + 0], ssum[0]);
        atomicAdd(&stats[bg * 2 + 1], ssq[0]);
    }
}

// ---------------------------------------------------------------------------
// normalize + affine + leaky_relu(0.2) + max over k=16
// ---------------------------------------------------------------------------
__global__ void norm_max_kernel(const float* __restrict__ Y,
                                const float* __restrict__ stats,
                                const float* __restrict__ gamma,
                                const float* __restrict__ beta,
                                int O, int Nq, float* __restrict__ out) {
    int i = blockIdx.x * blockDim.x + threadIdx.x;
    if (i >= 8 * O * Nq) return;
    int n = i % Nq;
    int o = (i / Nq) % O;
    int b = i / (Nq * O);
    int Cg = O >> 2;
    int g = o / Cg;
    float cntf = (float)((size_t)Cg * Nq * 16);
    float su = stats[(b * 4 + g) * 2 + 0];
    float sq = stats[(b * 4 + g) * 2 + 1];
    float mu = su / cntf;
    float var = sq / cntf - mu * mu;
    if (var < 0.f) var = 0.f;
    float rs = rsqrtf(var + 1e-5f);
    float a = gamma[o] * rs;
    float bb = __fmaf_rn(-mu, a, beta[o]);
    const float4* yp = reinterpret_cast<const float4*>(
        Y + (((size_t)b * O + o) * Nq + n) * 16);
    float mx = -3.4e38f;
#pragma unroll
    for (int k = 0; k < 4; k++) {
        float4 v4 = yp[k];
        float vv[4] = {v4.x, v4.y, v4.z, v4.w};
#pragma unroll
        for (int e = 0; e < 4; e++) {
            float v = __fmaf_rn(vv[e], a, bb);
            v = (v >= 0.f) ? v : 0.2f * v;
            mx = fmaxf(mx, v);
        }
    }
    out[((size_t)b * O + o) * Nq + n] = mx;
}

// ---------------------------------------------------------------------------
// final output: [coords (8,128,3)] ++ [features transposed (8,128,256)]
// ---------------------------------------------------------------------------
__global__ void write_out_kernel(const float* __restrict__ c3,
                                 const float* __restrict__ s3,
                                 float* __restrict__ out) {
    int i = blockIdx.x * blockDim.x + threadIdx.x;
    if (i >= 265216) return;
    if (i < 3072) {
        out[i] = c3[i];
    } else {
        int j = i - 3072;               // (b, n, c) row-major over (8,128,256)
        int c = j & 255;
        int n = (j >> 8) & 127;
        int b = j >> 15;
        out[i] = s3[((size_t)b * 256 + c) * 128 + n];
    }
}

// ---------------------------------------------------------------------------
// host-side layer driver
// ---------------------------------------------------------------------------
static void run_layer(const float* W, const float* gamma, const float* beta,
                      const float* xk, const float* xq, const int* idx,
                      int C, int Nq, int Nk, int O, float* fout,
                      float* edge, float* Y, float* stats) {
    int M = Nq * 16;
    int C2 = 2 * C;
    edge_kernel<<<dim3(M / 256, C2, B), 256>>>(xk, xq, idx, C, Nq, Nk, edge);
    gemm_kernel<<<dim3(M / 128, O / 32, B), 256>>>(W, edge, Y, O, C2, M);
    zero_stats_kernel<<<1, 64>>>(stats);
    stats_kernel<<<dim3(32, 32), 256>>>(Y, O, M, stats);
    int tot = 8 * O * Nq;
    norm_max_kernel<<<(tot + 255) / 256, 256>>>(Y, stats, gamma, beta, O, Nq, fout);
}

extern "C" void kernel_launch(void* const* d_in, const int* in_sizes, int n_in,
                              void* d_out, int out_size) {
    (void)in_sizes; (void)n_in; (void)out_size;
    const float* x    = (const float*)d_in[0];
    const float* w_in = (const float*)d_in[4];
    const float* b_in = (const float*)d_in[5];
    const float* w1 = (const float*)d_in[6];
    const float* g1 = (const float*)d_in[7];
    const float* e1 = (const float*)d_in[8];
    const float* w2 = (const float*)d_in[9];
    const float* g2 = (const float*)d_in[10];
    const float* e2 = (const float*)d_in[11];
    const float* w4 = (const float*)d_in[12];
    const float* g4 = (const float*)d_in[13];
    const float* e4 = (const float*)d_in[14];
    const float* w5 = (const float*)d_in[15];
    const float* g5 = (const float*)d_in[16];
    const float* e5 = (const float*)d_in[17];
    const float* w6 = (const float*)d_in[18];
    const float* g6 = (const float*)d_in[19];
    const float* e6 = (const float*)d_in[20];
    const float* w7 = (const float*)d_in[21];
    const float* g7 = (const float*)d_in[22];
    const float* e7 = (const float*)d_in[23];
    float* out = (float*)d_out;

    float* A = nullptr;
    cudaGetSymbolAddress((void**)&A, g_arena);

    float* edge  = A + OFF_EDGE;
    float* Y     = A + OFF_Y;
    float* f0    = A + OFF_F0;
    float* f1    = A + OFF_F1;
    float* f1q   = A + OFF_F1Q;
    float* s1    = A + OFF_S1;
    float* s1q   = A + OFF_S1Q;
    float* f4    = A + OFF_F4;
    float* s2    = A + OFF_S2;
    float* s2q   = A + OFF_S2Q;
    float* f6    = A + OFF_F6;
    float* s3    = A + OFF_S3;
    float* c1    = A + OFF_C1;
    float* c2    = A + OFF_C2;
    float* c3    = A + OFF_C3;
    float* stats = A + OFF_STATS;
    int*   sel   = (int*)(A + OFF_SEL);
    int*   knn   = (int*)(A + OFF_KNN);

    // input projection: f0 (8,8,4096)
    input_proj_kernel<<<(8 * 4096 + 255) / 256, 256>>>(x, w_in, b_in, f0);

    // ---- layer 1: self-graph on all 4096 points, C=8 -> O=32 ----
    knn_kernel<<<dim3(4096 / 128, B), 128>>>(x, x, 4096, 4096, knn);
    run_layer(w1, g1, e1, f0, f0, knn, 8, 4096, 4096, 32, f1, edge, Y, stats);

    // ---- FPS 4096 -> 2048 on original coords ----
    fps_kernel<4><<<B, 1024>>>(x, 4096, 2048, sel, c1);
    gather_feat_kernel<<<(8 * 32 * 2048 + 255) / 256, 256>>>(f1, sel, 32, 4096,
                                                             2048, f1q);

    // ---- layer 2: q=2048 downsampled, k=4096 full, C=32 -> O=64 ----
    knn_kernel<<<dim3(2048 / 128, B), 128>>>(c1, x, 2048, 4096, knn);
    run_layer(w2, g2, e2, f1, f1q, knn, 32, 2048, 4096, 64, s1, edge, Y, stats);

    // ---- FPS 2048 -> 512 ----
    fps_kernel<2><<<B, 1024>>>(c1, 2048, 512, sel, c2);
    gather_feat_kernel<<<(8 * 64 * 512 + 255) / 256, 256>>>(s1, sel, 64, 2048,
                                                            512, s1q);

    // ---- layer 4: q=512, k=2048, C=64 -> O=128 ----
    knn_kernel<<<dim3(512 / 128, B), 128>>>(c2, c1, 512, 2048, knn);
    run_layer(w4, g4, e4, s1, s1q, knn, 64, 512, 2048, 128, f4, edge, Y, stats);

    // ---- layer 5: self-graph on 512, C=128 -> O=128 ----
    knn_kernel<<<dim3(512 / 128, B), 128>>>(c2, c2, 512, 512, knn);
    run_layer(w5, g5, e5, f4, f4, knn, 128, 512, 512, 128, s2, edge, Y, stats);

    // ---- FPS 512 -> 128 ----
    fps_kernel<1><<<B, 1024>>>(c2, 512, 128, sel, c3);
    gather_feat_kernel<<<(8 * 128 * 128 + 255) / 256, 256>>>(s2, sel, 128, 512,
                                                             128, s2q);

    // ---- layer 6: q=128, k=512, C=128 -> O=256 ----
    knn_kernel<<<dim3(1, B), 128>>>(c3, c2, 128, 512, knn);
    run_layer(w6, g6, e6, s2, s2q, knn, 128, 128, 512, 256, f6, edge, Y, stats);

    // ---- layer 7: self-graph on 128, C=256 -> O=256 ----
    knn_kernel<<<dim3(1, B), 128>>>(c3, c3, 128, 128, knn);
    run_layer(w7, g7, e7, f6, f6, knn, 256, 128, 128, 256, s3, edge, Y, stats);

    // ---- output: coords then transposed features ----
    write_out_kernel<<<(265216 + 255) / 256, 256>>>(c3, s3, out);
}